// round 1
// baseline (speedup 1.0000x reference)
#include <cuda_runtime.h>
#include <cuda_bf16.h>
#include <cstdint>
#include <cstdio>

// Problem constants
#define BB   16384
#define DD   1024
#define EE   8
#define CC   50
#define RH   512
#define RH2  256
#define H1   2048
#define H2   1024
#define NSLOT (BB*2)

// ---------------- scratch (device globals; no allocations allowed) ----------
__device__ float g_h1r[BB*RH];           // router hidden 1
__device__ float g_h2r[BB*RH2];          // router hidden 2
__device__ float g_eh1[(size_t)NSLOT*H1];// expert hidden 1 (per slot)
__device__ float g_eh2[(size_t)NSLOT*H2];// expert hidden 2 (per slot)
__device__ int   g_rowtok[NSLOT];        // slot -> token
__device__ float g_rowgate[NSLOT];       // slot -> gate
__device__ int   g_topi[BB*2];
__device__ float g_topg[BB*2];
__device__ int   g_cnt[EE];
__device__ int   g_off[EE];
__device__ int   g_cur[EE];

// ---------------- init ------------------------------------------------------
__global__ void zero_counts_kernel() {
    int i = threadIdx.x;
    if (i < EE) g_cnt[i] = 0;
}

// ---------------- tiled SGEMM 128x128x8, 256 threads, 8x8 micro -------------
// C[off+row, n] = relu?( sum_k A[src(row),k]*W[e][k,n] + bias[e][n] )
// src(row) = GATHER ? rowtok[off+row] : off+row
template<bool GATHER>
__global__ __launch_bounds__(256) void sgemm_tiled(
    const float* __restrict__ A, const float* __restrict__ W,
    const float* __restrict__ bias, float* __restrict__ Cmat,
    int K, int N, int Mfixed,
    const int* __restrict__ off_arr, const int* __restrict__ cnt_arr,
    const int* __restrict__ rowtok,
    long wstride, int bstride, int relu)
{
    const int e   = blockIdx.z;
    const int cnt = cnt_arr ? cnt_arr[e] : Mfixed;
    const int row0 = blockIdx.y * 128;
    if (row0 >= cnt) return;
    const int off = off_arr ? off_arr[e] : 0;
    const float* We = W + (long)e * wstride;
    const float* be = bias + (long)e * bstride;
    const int n0 = blockIdx.x * 128;

    __shared__ float As[8][128];
    __shared__ float Bs[8][128];

    const int tid = threadIdx.x;
    const int tx = tid & 15;       // 0..15 (cols)
    const int ty = tid >> 4;       // 0..15 (rows)

    float acc[8][8];
    #pragma unroll
    for (int i = 0; i < 8; i++)
        #pragma unroll
        for (int j = 0; j < 8; j++) acc[i][j] = 0.f;

    // A-tile loader mapping: each thread loads one float4
    const int lm  = tid >> 1;        // 0..127 (m within tile)
    const int lkq = (tid & 1) * 4;   // 0 or 4 (k offset)
    int rloc = row0 + lm;
    if (rloc > cnt - 1) rloc = cnt - 1;
    int src;
    if (GATHER) src = rowtok[off + rloc];
    else        src = off + rloc;
    const float* Arow = A + (size_t)src * K;

    // B-tile loader mapping
    const int bk = tid >> 5;         // 0..7
    const int bn = (tid & 31) * 4;   // 0..124

    for (int k0 = 0; k0 < K; k0 += 8) {
        float4 av = *(const float4*)(Arow + k0 + lkq);
        As[lkq + 0][lm] = av.x;
        As[lkq + 1][lm] = av.y;
        As[lkq + 2][lm] = av.z;
        As[lkq + 3][lm] = av.w;
        float4 bv = *(const float4*)(We + (size_t)(k0 + bk) * N + n0 + bn);
        *(float4*)&Bs[bk][bn] = bv;
        __syncthreads();

        #pragma unroll
        for (int kk = 0; kk < 8; kk++) {
            float a[8], b[8];
            #pragma unroll
            for (int i = 0; i < 8; i++) a[i] = As[kk][ty * 8 + i];
            #pragma unroll
            for (int j = 0; j < 8; j++) b[j] = Bs[kk][tx * 8 + j];
            #pragma unroll
            for (int i = 0; i < 8; i++)
                #pragma unroll
                for (int j = 0; j < 8; j++)
                    acc[i][j] += a[i] * b[j];
        }
        __syncthreads();
    }

    // epilogue
    #pragma unroll
    for (int i = 0; i < 8; i++) {
        int r = row0 + ty * 8 + i;
        if (r >= cnt) continue;
        size_t crow = (size_t)(off + r);
        #pragma unroll
        for (int j = 0; j < 8; j += 4) {
            int n = n0 + tx * 8 + j;
            float4 v;
            v.x = acc[i][j + 0] + be[n + 0];
            v.y = acc[i][j + 1] + be[n + 1];
            v.z = acc[i][j + 2] + be[n + 2];
            v.w = acc[i][j + 3] + be[n + 3];
            if (relu) {
                v.x = fmaxf(v.x, 0.f); v.y = fmaxf(v.y, 0.f);
                v.z = fmaxf(v.z, 0.f); v.w = fmaxf(v.w, 0.f);
            }
            *(float4*)(Cmat + crow * N + n) = v;
        }
    }
}

// ---------------- router GEMM3 + softmax + top2 -----------------------------
// 256 threads: 32 tokens x 8 experts per block
__global__ __launch_bounds__(256) void router3_softmax_topk(
    const float* __restrict__ h2, const float* __restrict__ W3,
    const float* __restrict__ b3, float* __restrict__ probs_out)
{
    __shared__ float sh[32][RH2];
    __shared__ float sc[32][EE];
    const int tid = threadIdx.x;
    const int t0 = blockIdx.x * 32;

    for (int i = tid; i < 32 * RH2; i += 256) {
        int r = i >> 8;          // RH2 == 256
        int c = i & 255;
        sh[r][c] = h2[(size_t)(t0 + r) * RH2 + c];
    }
    __syncthreads();

    const int tok = tid >> 3;   // 0..31
    const int e   = tid & 7;    // 0..7
    float s = b3[e];
    #pragma unroll 8
    for (int k = 0; k < RH2; k++)
        s += sh[tok][k] * W3[k * EE + e];
    sc[tok][e] = s;
    __syncthreads();

    if (e == 0) {
        const int t = t0 + tok;
        // softmax over 8
        float mx = sc[tok][0];
        #pragma unroll
        for (int i = 1; i < EE; i++) mx = fmaxf(mx, sc[tok][i]);
        float p[EE]; float sum = 0.f;
        #pragma unroll
        for (int i = 0; i < EE; i++) { p[i] = __expf(sc[tok][i] - mx); sum += p[i]; }
        float inv = 1.f / sum;
        #pragma unroll
        for (int i = 0; i < EE; i++) {
            p[i] *= inv;
            probs_out[(size_t)t * EE + i] = p[i];
        }
        // top-2 (first-index tie break, matching lax.top_k)
        int i1 = 0;
        #pragma unroll
        for (int i = 1; i < EE; i++) if (p[i] > p[i1]) i1 = i;
        int i2 = (i1 == 0) ? 1 : 0;
        #pragma unroll
        for (int i = 0; i < EE; i++) {
            if (i == i1) continue;
            if (p[i] > p[i2]) i2 = i;
        }
        g_topi[t * 2 + 0] = i1;
        g_topi[t * 2 + 1] = i2;
        g_topg[t * 2 + 0] = p[i1] * 0.5f;
        g_topg[t * 2 + 1] = p[i2] * 0.5f;
        atomicAdd(&g_cnt[i1], 1);
        atomicAdd(&g_cnt[i2], 1);
    }
}

// ---------------- offsets + scatter -----------------------------------------
__global__ void offsets_kernel() {
    if (threadIdx.x == 0) {
        int acc = 0;
        #pragma unroll
        for (int e = 0; e < EE; e++) {
            g_off[e] = acc;
            acc += g_cnt[e];
            g_cur[e] = 0;
        }
    }
}

__global__ void scatter_kernel() {
    int t = blockIdx.x * blockDim.x + threadIdx.x;
    if (t >= BB) return;
    #pragma unroll
    for (int k = 0; k < 2; k++) {
        int e = g_topi[t * 2 + k];
        int p = atomicAdd(&g_cur[e], 1);
        int s = g_off[e] + p;
        g_rowtok[s]  = t;
        g_rowgate[s] = g_topg[t * 2 + k];
    }
}

// ---------------- expert layer 3 + gated combine ----------------------------
// block: 256 threads = 4 rows x 64 lanes; K=1024, N=50
__global__ __launch_bounds__(256) void expert_l3_combine(
    const float* __restrict__ h2buf, const float* __restrict__ W3all,
    const float* __restrict__ b3all, float* __restrict__ out)
{
    const int e = blockIdx.z;
    const int cnt = g_cnt[e];
    const int row0 = blockIdx.y * 4;
    if (row0 >= cnt) return;
    const int off = g_off[e];

    __shared__ float sh[4][H2];
    const int tid = threadIdx.x;
    for (int i = tid; i < 4 * H2; i += 256) {
        int r = i >> 10;         // H2 == 1024
        int c = i & 1023;
        int rl = row0 + r;
        sh[r][c] = (rl < cnt) ? h2buf[(size_t)(off + rl) * H2 + c] : 0.f;
    }
    __syncthreads();

    const int r = tid >> 6;      // 0..3
    const int lane = tid & 63;   // 0..63
    const int rl = row0 + r;
    if (lane < CC && rl < cnt) {
        const float* W3 = W3all + (size_t)e * H2 * CC;
        float s = b3all[e * CC + lane];
        #pragma unroll 8
        for (int k = 0; k < H2; k++)
            s += sh[r][k] * W3[k * CC + lane];
        int slot = off + rl;
        int tok = g_rowtok[slot];
        float g = g_rowgate[slot];
        atomicAdd(&out[(size_t)tok * CC + lane], g * s);
    }
}

// ---------------- launch ----------------------------------------------------
extern "C" void kernel_launch(void* const* d_in, const int* in_sizes, int n_in,
                              void* d_out, int out_size)
{
    const float* x   = (const float*)d_in[0];
    const float* rW1 = (const float*)d_in[1];
    const float* rb1 = (const float*)d_in[2];
    const float* rW2 = (const float*)d_in[3];
    const float* rb2 = (const float*)d_in[4];
    const float* rW3 = (const float*)d_in[5];
    const float* rb3 = (const float*)d_in[6];
    const float* eW1 = (const float*)d_in[7];
    const float* eb1 = (const float*)d_in[8];
    const float* eW2 = (const float*)d_in[9];
    const float* eb2 = (const float*)d_in[10];
    const float* eW3 = (const float*)d_in[11];
    const float* eb3 = (const float*)d_in[12];
    (void)n_in; (void)in_sizes;

    float* out_final = (float*)d_out;                 // [B, C]
    float* out_probs = (float*)d_out + (size_t)BB * CC; // [B, E]

    // zero final output (atomic combine target); probs are overwritten anyway
    cudaMemsetAsync(d_out, 0, (size_t)out_size * sizeof(float));
    zero_counts_kernel<<<1, 32>>>();

    float* h1r; cudaGetSymbolAddress((void**)&h1r, g_h1r);
    float* h2r; cudaGetSymbolAddress((void**)&h2r, g_h2r);
    float* eh1; cudaGetSymbolAddress((void**)&eh1, g_eh1);
    float* eh2; cudaGetSymbolAddress((void**)&eh2, g_eh2);
    int*   rowtok; cudaGetSymbolAddress((void**)&rowtok, g_rowtok);
    int*   cntp; cudaGetSymbolAddress((void**)&cntp, g_cnt);
    int*   offp; cudaGetSymbolAddress((void**)&offp, g_off);

    // Router GEMM1: [B,1024] x [1024,512] -> relu
    {
        dim3 grid(RH / 128, BB / 128, 1);
        sgemm_tiled<false><<<grid, 256>>>(x, rW1, rb1, h1r,
            DD, RH, BB, nullptr, nullptr, nullptr, 0L, 0, 1);
    }
    // Router GEMM2: [B,512] x [512,256] -> relu
    {
        dim3 grid(RH2 / 128, BB / 128, 1);
        sgemm_tiled<false><<<grid, 256>>>(h1r, rW2, rb2, h2r,
            RH, RH2, BB, nullptr, nullptr, nullptr, 0L, 0, 1);
    }
    // Router GEMM3 + softmax + top2 + counts
    router3_softmax_topk<<<BB / 32, 256>>>(h2r, rW3, rb3, out_probs);
    // Offsets + scatter
    offsets_kernel<<<1, 32>>>();
    scatter_kernel<<<BB / 256, 256>>>();

    // Expert L1: gather x rows -> [cnt, 2048] relu
    {
        dim3 grid(H1 / 128, BB / 128, EE);
        sgemm_tiled<true><<<grid, 256>>>(x, eW1, eb1, eh1,
            DD, H1, 0, offp, cntp, rowtok, (long)DD * H1, H1, 1);
    }
    // Expert L2: [cnt, 2048] x [2048, 1024] relu
    {
        dim3 grid(H2 / 128, BB / 128, EE);
        sgemm_tiled<false><<<grid, 256>>>(eh1, eW2, eb2, eh2,
            H1, H2, 0, offp, cntp, nullptr, (long)H1 * H2, H2, 1);
    }
    // Expert L3 + gated atomic combine
    {
        dim3 grid(1, BB / 4, EE);
        expert_l3_combine<<<grid, 256>>>(eh2, eW3, eb3, out_final);
    }
}

// round 4
// speedup vs baseline: 1.2530x; 1.2530x over previous
#include <cuda_runtime.h>
#include <cuda_bf16.h>
#include <cstdint>

// Problem constants
#define BB   16384
#define DD   1024
#define EE   8
#define CC   50
#define RH   512
#define RH2  256
#define H1   2048
#define H2   1024
#define NSLOT (BB*2)

// GEMM tiling
#define KC    32          // k-chunk
#define RS    40          // smem row stride in bf16 (80B, conflict-free)
#define ARR_B (128*RS*2)  // bytes per smem array = 10240
#define STG_B (4*ARR_B)   // bytes per stage     = 40960
#define GEMM_SMEM (2*STG_B)

// ---------------- device scratch (no allocations allowed) -------------------
__device__ __align__(256) __nv_bfloat16 g_xhi[(size_t)BB*DD];
__device__ __align__(256) __nv_bfloat16 g_xlo[(size_t)BB*DD];
__device__ __align__(256) __nv_bfloat16 g_h1hi[(size_t)BB*RH];
__device__ __align__(256) __nv_bfloat16 g_h1lo[(size_t)BB*RH];
__device__ __align__(256) float         g_h2[(size_t)BB*RH2];
__device__ __align__(256) __nv_bfloat16 g_rw1t_hi[(size_t)RH*DD];
__device__ __align__(256) __nv_bfloat16 g_rw1t_lo[(size_t)RH*DD];
__device__ __align__(256) __nv_bfloat16 g_rw2t_hi[(size_t)RH2*RH];
__device__ __align__(256) __nv_bfloat16 g_rw2t_lo[(size_t)RH2*RH];
__device__ __align__(256) __nv_bfloat16 g_ew1t_hi[(size_t)EE*H1*DD];
__device__ __align__(256) __nv_bfloat16 g_ew1t_lo[(size_t)EE*H1*DD];
__device__ __align__(256) __nv_bfloat16 g_ew2t_hi[(size_t)EE*H2*H1];
__device__ __align__(256) __nv_bfloat16 g_ew2t_lo[(size_t)EE*H2*H1];
__device__ __align__(256) __nv_bfloat16 g_eh1hi[(size_t)NSLOT*H1];
__device__ __align__(256) __nv_bfloat16 g_eh1lo[(size_t)NSLOT*H1];
__device__ __align__(256) float         g_eh2[(size_t)NSLOT*H2];
__device__ int   g_rowtok[NSLOT];
__device__ float g_rowgate[NSLOT];
__device__ int   g_topi[BB*2];
__device__ float g_topg[BB*2];
__device__ int   g_cnt[EE];
__device__ int   g_off[EE];
__device__ int   g_cur[EE];

// ---------------- helpers ----------------------------------------------------
__device__ __forceinline__ uint32_t smem_u32(const void* p) {
    return (uint32_t)__cvta_generic_to_shared(p);
}
__device__ __forceinline__ void cp16(uint32_t saddr, const void* gptr) {
    asm volatile("cp.async.ca.shared.global [%0], [%1], 16;\n"
                 :: "r"(saddr), "l"(gptr));
}
__device__ __forceinline__ void cp_commit() {
    asm volatile("cp.async.commit_group;\n" ::: "memory");
}
template<int N>
__device__ __forceinline__ void cp_wait() {
    asm volatile("cp.async.wait_group %0;\n" :: "n"(N) : "memory");
}
__device__ __forceinline__ void mma_bf16(float* c,
    uint32_t a0, uint32_t a1, uint32_t a2, uint32_t a3,
    uint32_t b0, uint32_t b1)
{
    asm volatile(
        "mma.sync.aligned.m16n8k16.row.col.f32.bf16.bf16.f32 "
        "{%0,%1,%2,%3}, {%4,%5,%6,%7}, {%8,%9}, {%0,%1,%2,%3};\n"
        : "+f"(c[0]), "+f"(c[1]), "+f"(c[2]), "+f"(c[3])
        : "r"(a0), "r"(a1), "r"(a2), "r"(a3), "r"(b0), "r"(b1));
}
__device__ __forceinline__ uint32_t bf2u(__nv_bfloat16 a, __nv_bfloat16 b) {
    __nv_bfloat162 p; p.x = a; p.y = b;
    return *reinterpret_cast<uint32_t*>(&p);
}

// ---------------- init ------------------------------------------------------
__global__ void zero_counts_kernel() {
    int i = threadIdx.x;
    if (i < EE) g_cnt[i] = 0;
}

// ---------------- fp32 -> bf16 hi/lo split ----------------------------------
__global__ void split_x_kernel(const float* __restrict__ in,
    __nv_bfloat16* __restrict__ hi, __nv_bfloat16* __restrict__ lo, size_t n)
{
    size_t i = ((size_t)blockIdx.x * 256 + threadIdx.x) * 4;
    if (i >= n) return;
    float4 v = *(const float4*)(in + i);
    float vv[4] = {v.x, v.y, v.z, v.w};
    __nv_bfloat16 h[4], l[4];
    #pragma unroll
    for (int u = 0; u < 4; u++) {
        h[u] = __float2bfloat16(vv[u]);
        l[u] = __float2bfloat16(vv[u] - __bfloat162float(h[u]));
    }
    uint2 ph, pl;
    ph.x = bf2u(h[0], h[1]); ph.y = bf2u(h[2], h[3]);
    pl.x = bf2u(l[0], l[1]); pl.y = bf2u(l[2], l[3]);
    *(uint2*)(hi + i) = ph;
    *(uint2*)(lo + i) = pl;
}

// ---------------- transpose + split W[K,N] -> T[N,K] hi/lo ------------------
__global__ void transpose_split_kernel(const float* __restrict__ W,
    __nv_bfloat16* __restrict__ Thi, __nv_bfloat16* __restrict__ Tlo,
    int K, int N)
{
    __shared__ float t[32][33];
    const size_t esz = (size_t)K * N;
    const float* We = W + (size_t)blockIdx.z * esz;
    __nv_bfloat16* Th = Thi + (size_t)blockIdx.z * esz;
    __nv_bfloat16* Tl = Tlo + (size_t)blockIdx.z * esz;
    int n0 = blockIdx.x * 32, k0 = blockIdx.y * 32;
    int tx = threadIdx.x, ty = threadIdx.y;
    #pragma unroll
    for (int r = 0; r < 32; r += 8)
        t[ty + r][tx] = We[(size_t)(k0 + ty + r) * N + n0 + tx];
    __syncthreads();
    #pragma unroll
    for (int r = 0; r < 32; r += 8) {
        float v = t[tx][ty + r];
        __nv_bfloat16 h = __float2bfloat16(v);
        __nv_bfloat16 l = __float2bfloat16(v - __bfloat162float(h));
        size_t o = (size_t)(n0 + ty + r) * K + (k0 + tx);
        Th[o] = h; Tl[o] = l;
    }
}

// ---------------- HMMA split-bf16 GEMM --------------------------------------
// C[off+m, n] = relu( sum_k A[src(m),k] * Wt[e][n,k] + bias[e][n] )
// 128x128 block tile, 8 warps (4x2), warp tile 32x64, K-chunk 32,
// 2-stage cp.async pipeline, 3-MMA hi/lo split.
template<bool GATHER, bool HILO>
__global__ __launch_bounds__(256) void gemm_mma(
    const __nv_bfloat16* __restrict__ Ahi, const __nv_bfloat16* __restrict__ Alo,
    const __nv_bfloat16* __restrict__ Whi, const __nv_bfloat16* __restrict__ Wlo,
    const float* __restrict__ bias,
    float* __restrict__ outF,
    __nv_bfloat16* __restrict__ outHi, __nv_bfloat16* __restrict__ outLo,
    int K, int N, int Mfixed,
    const int* __restrict__ off_arr, const int* __restrict__ cnt_arr,
    const int* __restrict__ rowtok,
    long wstride, int bstride)
{
    const int e   = blockIdx.z;
    const int cnt = cnt_arr ? cnt_arr[e] : Mfixed;
    const int row0 = blockIdx.y * 128;
    if (row0 >= cnt) return;
    const int off = off_arr ? off_arr[e] : 0;
    const int n0 = blockIdx.x * 128;

    extern __shared__ char smem[];
    __shared__ float sbias[128];
    const uint32_t smem_base = smem_u32(smem);
    const int tid = threadIdx.x;

    const __nv_bfloat16* We_hi = Whi + (size_t)e * wstride;
    const __nv_bfloat16* We_lo = Wlo + (size_t)e * wstride;
    const float* be = bias + (size_t)e * bstride;
    if (tid < 128) sbias[tid] = be[n0 + tid];

    // global load mapping: thread -> (row, 2 x 16B segments)
    const int lrow = tid >> 1;            // 0..127
    const int lseg = (tid & 1) * 2;       // 0 or 2
    int rloc = row0 + lrow; if (rloc > cnt - 1) rloc = cnt - 1;
    const int srcA = GATHER ? rowtok[off + rloc] : off + rloc;
    const __nv_bfloat16* pAhi = Ahi + (size_t)srcA * K;
    const __nv_bfloat16* pAlo = Alo + (size_t)srcA * K;
    const __nv_bfloat16* pBhi = We_hi + (size_t)(n0 + lrow) * K;
    const __nv_bfloat16* pBlo = We_lo + (size_t)(n0 + lrow) * K;
    const uint32_t srow = lrow * (RS * 2);   // byte offset of row in each array

    const int nch = K / KC;

    // warp/lane decomposition
    const int lane = tid & 31;
    const int wid  = tid >> 5;
    const int warp_m = wid >> 1;          // 0..3
    const int warp_n = wid & 1;           // 0..1
    const int g  = lane >> 2;             // 0..7
    const int tg = lane & 3;              // 0..3

    float acc[2][8][4];
    #pragma unroll
    for (int mt = 0; mt < 2; mt++)
        #pragma unroll
        for (int nt = 0; nt < 8; nt++)
            #pragma unroll
            for (int q = 0; q < 4; q++) acc[mt][nt][q] = 0.f;

    // ---- issue loads for chunk 0 ----
    {
        const size_t k0 = 0;
        const uint32_t sb = smem_base;
        #pragma unroll
        for (int s = 0; s < 2; s++) {
            int seg = lseg + s;
            uint32_t so = srow + seg * 16;
            cp16(sb + 0*ARR_B + so, pAhi + k0 + seg * 8);
            cp16(sb + 1*ARR_B + so, pAlo + k0 + seg * 8);
            cp16(sb + 2*ARR_B + so, pBhi + k0 + seg * 8);
            cp16(sb + 3*ARR_B + so, pBlo + k0 + seg * 8);
        }
        cp_commit();
    }

    for (int i = 0; i < nch; i++) {
        if (i + 1 < nch) {
            const size_t k0 = (size_t)(i + 1) * KC;
            const uint32_t sb = smem_base + ((i + 1) & 1) * STG_B;
            #pragma unroll
            for (int s = 0; s < 2; s++) {
                int seg = lseg + s;
                uint32_t so = srow + seg * 16;
                cp16(sb + 0*ARR_B + so, pAhi + k0 + seg * 8);
                cp16(sb + 1*ARR_B + so, pAlo + k0 + seg * 8);
                cp16(sb + 2*ARR_B + so, pBhi + k0 + seg * 8);
                cp16(sb + 3*ARR_B + so, pBlo + k0 + seg * 8);
            }
            cp_commit();
            cp_wait<1>();
        } else {
            cp_wait<0>();
        }
        __syncthreads();

        const char* st = smem + (i & 1) * STG_B;
        const __nv_bfloat16* sAhi = (const __nv_bfloat16*)(st);
        const __nv_bfloat16* sAlo = (const __nv_bfloat16*)(st + ARR_B);
        const __nv_bfloat16* sBhi = (const __nv_bfloat16*)(st + 2*ARR_B);
        const __nv_bfloat16* sBlo = (const __nv_bfloat16*)(st + 3*ARR_B);

        #pragma unroll
        for (int kk = 0; kk < KC; kk += 16) {
            // A fragments: [mt][hi/lo][4]
            uint32_t af[2][2][4];
            #pragma unroll
            for (int mt = 0; mt < 2; mt++) {
                int mrow = warp_m * 32 + mt * 16 + g;
                const __nv_bfloat16* r0h = sAhi + (size_t)mrow * RS + kk + tg * 2;
                const __nv_bfloat16* r1h = r0h + 8 * RS;
                const __nv_bfloat16* r0l = sAlo + (size_t)mrow * RS + kk + tg * 2;
                const __nv_bfloat16* r1l = r0l + 8 * RS;
                af[mt][0][0] = *(const uint32_t*)(r0h);
                af[mt][0][1] = *(const uint32_t*)(r1h);
                af[mt][0][2] = *(const uint32_t*)(r0h + 8);
                af[mt][0][3] = *(const uint32_t*)(r1h + 8);
                af[mt][1][0] = *(const uint32_t*)(r0l);
                af[mt][1][1] = *(const uint32_t*)(r1l);
                af[mt][1][2] = *(const uint32_t*)(r0l + 8);
                af[mt][1][3] = *(const uint32_t*)(r1l + 8);
            }
            #pragma unroll
            for (int nt = 0; nt < 8; nt++) {
                int nrow = warp_n * 64 + nt * 8 + g;
                const __nv_bfloat16* bh = sBhi + (size_t)nrow * RS + kk + tg * 2;
                const __nv_bfloat16* bl = sBlo + (size_t)nrow * RS + kk + tg * 2;
                uint32_t bh0 = *(const uint32_t*)(bh);
                uint32_t bh1 = *(const uint32_t*)(bh + 8);
                uint32_t bl0 = *(const uint32_t*)(bl);
                uint32_t bl1 = *(const uint32_t*)(bl + 8);
                #pragma unroll
                for (int mt = 0; mt < 2; mt++) {
                    mma_bf16(acc[mt][nt], af[mt][0][0], af[mt][0][1], af[mt][0][2], af[mt][0][3], bh0, bh1);
                    mma_bf16(acc[mt][nt], af[mt][0][0], af[mt][0][1], af[mt][0][2], af[mt][0][3], bl0, bl1);
                    mma_bf16(acc[mt][nt], af[mt][1][0], af[mt][1][1], af[mt][1][2], af[mt][1][3], bh0, bh1);
                }
            }
        }
        __syncthreads();
    }

    // ---- epilogue ----
    #pragma unroll
    for (int mt = 0; mt < 2; mt++) {
        #pragma unroll
        for (int half = 0; half < 2; half++) {
            const int grow = row0 + warp_m * 32 + mt * 16 + g + half * 8;
            if (grow >= cnt) continue;
            const size_t orow = (size_t)(off + grow);
            #pragma unroll
            for (int nt = 0; nt < 8; nt++) {
                const int col = warp_n * 64 + nt * 8 + tg * 2;
                float v0 = acc[mt][nt][half * 2 + 0] + sbias[col];
                float v1 = acc[mt][nt][half * 2 + 1] + sbias[col + 1];
                v0 = fmaxf(v0, 0.f);
                v1 = fmaxf(v1, 0.f);
                if (HILO) {
                    __nv_bfloat16 h0 = __float2bfloat16(v0);
                    __nv_bfloat16 h1 = __float2bfloat16(v1);
                    __nv_bfloat16 l0 = __float2bfloat16(v0 - __bfloat162float(h0));
                    __nv_bfloat16 l1 = __float2bfloat16(v1 - __bfloat162float(h1));
                    *(uint32_t*)(outHi + orow * N + n0 + col) = bf2u(h0, h1);
                    *(uint32_t*)(outLo + orow * N + n0 + col) = bf2u(l0, l1);
                } else {
                    float2 v; v.x = v0; v.y = v1;
                    *(float2*)(outF + orow * N + n0 + col) = v;
                }
            }
        }
    }
}

// ---------------- router GEMM3 + softmax + top2 -----------------------------
__global__ __launch_bounds__(256) void router3_softmax_topk(
    const float* __restrict__ h2, const float* __restrict__ W3,
    const float* __restrict__ b3, float* __restrict__ probs_out)
{
    __shared__ float sh[32][RH2];
    __shared__ float sc[32][EE];
    const int tid = threadIdx.x;
    const int t0 = blockIdx.x * 32;

    for (int i = tid; i < 32 * RH2; i += 256) {
        int r = i >> 8;
        int c = i & 255;
        sh[r][c] = h2[(size_t)(t0 + r) * RH2 + c];
    }
    __syncthreads();

    const int tok = tid >> 3;
    const int e   = tid & 7;
    float s = b3[e];
    #pragma unroll 8
    for (int k = 0; k < RH2; k++)
        s += sh[tok][k] * W3[k * EE + e];
    sc[tok][e] = s;
    __syncthreads();

    if (e == 0) {
        const int t = t0 + tok;
        float mx = sc[tok][0];
        #pragma unroll
        for (int i = 1; i < EE; i++) mx = fmaxf(mx, sc[tok][i]);
        float p[EE]; float sum = 0.f;
        #pragma unroll
        for (int i = 0; i < EE; i++) { p[i] = __expf(sc[tok][i] - mx); sum += p[i]; }
        float inv = 1.f / sum;
        #pragma unroll
        for (int i = 0; i < EE; i++) {
            p[i] *= inv;
            probs_out[(size_t)t * EE + i] = p[i];
        }
        int i1 = 0;
        #pragma unroll
        for (int i = 1; i < EE; i++) if (p[i] > p[i1]) i1 = i;
        int i2 = (i1 == 0) ? 1 : 0;
        #pragma unroll
        for (int i = 0; i < EE; i++) {
            if (i == i1) continue;
            if (p[i] > p[i2]) i2 = i;
        }
        g_topi[t * 2 + 0] = i1;
        g_topi[t * 2 + 1] = i2;
        g_topg[t * 2 + 0] = p[i1] * 0.5f;
        g_topg[t * 2 + 1] = p[i2] * 0.5f;
        atomicAdd(&g_cnt[i1], 1);
        atomicAdd(&g_cnt[i2], 1);
    }
}

// ---------------- offsets + scatter -----------------------------------------
__global__ void offsets_kernel() {
    if (threadIdx.x == 0) {
        int acc = 0;
        #pragma unroll
        for (int e = 0; e < EE; e++) {
            g_off[e] = acc;
            acc += g_cnt[e];
            g_cur[e] = 0;
        }
    }
}

__global__ void scatter_kernel() {
    int t = blockIdx.x * blockDim.x + threadIdx.x;
    if (t >= BB) return;
    #pragma unroll
    for (int k = 0; k < 2; k++) {
        int e = g_topi[t * 2 + k];
        int p = atomicAdd(&g_cur[e], 1);
        int s = g_off[e] + p;
        g_rowtok[s]  = t;
        g_rowgate[s] = g_topg[t * 2 + k];
    }
}

// ---------------- expert layer 3 + gated combine ----------------------------
__global__ __launch_bounds__(256) void expert_l3_combine(
    const float* __restrict__ h2buf, const float* __restrict__ W3all,
    const float* __restrict__ b3all, float* __restrict__ out)
{
    const int e = blockIdx.z;
    const int cnt = g_cnt[e];
    const int row0 = blockIdx.y * 4;
    if (row0 >= cnt) return;
    const int off = g_off[e];

    __shared__ float sh[4][H2];
    const int tid = threadIdx.x;
    for (int i = tid; i < 4 * H2; i += 256) {
        int r = i >> 10;
        int c = i & 1023;
        int rl = row0 + r;
        sh[r][c] = (rl < cnt) ? h2buf[(size_t)(off + rl) * H2 + c] : 0.f;
    }
    __syncthreads();

    const int r = tid >> 6;
    const int lane = tid & 63;
    const int rl = row0 + r;
    if (lane < CC && rl < cnt) {
        const float* W3 = W3all + (size_t)e * H2 * CC;
        float s = b3all[e * CC + lane];
        #pragma unroll 8
        for (int k = 0; k < H2; k++)
            s += sh[r][k] * W3[k * CC + lane];
        int slot = off + rl;
        int tok = g_rowtok[slot];
        float g = g_rowgate[slot];
        atomicAdd(&out[(size_t)tok * CC + lane], g * s);
    }
}

// ---------------- launch ----------------------------------------------------
extern "C" void kernel_launch(void* const* d_in, const int* in_sizes, int n_in,
                              void* d_out, int out_size)
{
    const float* x   = (const float*)d_in[0];
    const float* rW1 = (const float*)d_in[1];
    const float* rb1 = (const float*)d_in[2];
    const float* rW2 = (const float*)d_in[3];
    const float* rb2 = (const float*)d_in[4];
    const float* rW3 = (const float*)d_in[5];
    const float* rb3 = (const float*)d_in[6];
    const float* eW1 = (const float*)d_in[7];
    const float* eb1 = (const float*)d_in[8];
    const float* eW2 = (const float*)d_in[9];
    const float* eb2 = (const float*)d_in[10];
    const float* eW3 = (const float*)d_in[11];
    const float* eb3 = (const float*)d_in[12];
    (void)n_in; (void)in_sizes;

    float* out_final = (float*)d_out;
    float* out_probs = (float*)d_out + (size_t)BB * CC;

    cudaFuncSetAttribute(gemm_mma<false, true>,  cudaFuncAttributeMaxDynamicSharedMemorySize, GEMM_SMEM);
    cudaFuncSetAttribute(gemm_mma<false, false>, cudaFuncAttributeMaxDynamicSharedMemorySize, GEMM_SMEM);
    cudaFuncSetAttribute(gemm_mma<true, true>,   cudaFuncAttributeMaxDynamicSharedMemorySize, GEMM_SMEM);

    cudaMemsetAsync(d_out, 0, (size_t)out_size * sizeof(float));
    zero_counts_kernel<<<1, 32>>>();

    __nv_bfloat16 *xhi, *xlo, *h1hi, *h1lo;
    __nv_bfloat16 *rw1h, *rw1l, *rw2h, *rw2l, *ew1h, *ew1l, *ew2h, *ew2l;
    __nv_bfloat16 *eh1h, *eh1l;
    float *h2, *eh2;
    int *rowtokp, *cntp, *offp;
    cudaGetSymbolAddress((void**)&xhi,  g_xhi);   cudaGetSymbolAddress((void**)&xlo,  g_xlo);
    cudaGetSymbolAddress((void**)&h1hi, g_h1hi);  cudaGetSymbolAddress((void**)&h1lo, g_h1lo);
    cudaGetSymbolAddress((void**)&h2,   g_h2);
    cudaGetSymbolAddress((void**)&rw1h, g_rw1t_hi); cudaGetSymbolAddress((void**)&rw1l, g_rw1t_lo);
    cudaGetSymbolAddress((void**)&rw2h, g_rw2t_hi); cudaGetSymbolAddress((void**)&rw2l, g_rw2t_lo);
    cudaGetSymbolAddress((void**)&ew1h, g_ew1t_hi); cudaGetSymbolAddress((void**)&ew1l, g_ew1t_lo);
    cudaGetSymbolAddress((void**)&ew2h, g_ew2t_hi); cudaGetSymbolAddress((void**)&ew2l, g_ew2t_lo);
    cudaGetSymbolAddress((void**)&eh1h, g_eh1hi); cudaGetSymbolAddress((void**)&eh1l, g_eh1lo);
    cudaGetSymbolAddress((void**)&eh2,  g_eh2);
    cudaGetSymbolAddress((void**)&rowtokp, g_rowtok);
    cudaGetSymbolAddress((void**)&cntp, g_cnt);
    cudaGetSymbolAddress((void**)&offp, g_off);

    // input + weight conversion (hi/lo split, weights transposed to [N,K])
    split_x_kernel<<<(BB * DD) / 1024, 256>>>(x, xhi, xlo, (size_t)BB * DD);
    {
        dim3 g(RH / 32, DD / 32, 1);
        transpose_split_kernel<<<g, dim3(32, 8)>>>(rW1, rw1h, rw1l, DD, RH);
    }
    {
        dim3 g(RH2 / 32, RH / 32, 1);
        transpose_split_kernel<<<g, dim3(32, 8)>>>(rW2, rw2h, rw2l, RH, RH2);
    }
    {
        dim3 g(H1 / 32, DD / 32, EE);
        transpose_split_kernel<<<g, dim3(32, 8)>>>(eW1, ew1h, ew1l, DD, H1);
    }
    {
        dim3 g(H2 / 32, H1 / 32, EE);
        transpose_split_kernel<<<g, dim3(32, 8)>>>(eW2, ew2h, ew2l, H1, H2);
    }

    // Router L1: [B,1024]x[1024,512] -> h1 (hi/lo)
    {
        dim3 grid(RH / 128, BB / 128, 1);
        gemm_mma<false, true><<<grid, 256, GEMM_SMEM>>>(
            xhi, xlo, rw1h, rw1l, rb1, nullptr, h1hi, h1lo,
            DD, RH, BB, nullptr, nullptr, nullptr, 0L, 0);
    }
    // Router L2: [B,512]x[512,256] -> h2 (fp32)
    {
        dim3 grid(RH2 / 128, BB / 128, 1);
        gemm_mma<false, false><<<grid, 256, GEMM_SMEM>>>(
            h1hi, h1lo, rw2h, rw2l, rb2, h2, nullptr, nullptr,
            RH, RH2, BB, nullptr, nullptr, nullptr, 0L, 0);
    }
    // Router L3 + softmax + top2
    router3_softmax_topk<<<BB / 32, 256>>>(h2, rW3, rb3, out_probs);
    offsets_kernel<<<1, 32>>>();
    scatter_kernel<<<BB / 256, 256>>>();

    // Expert L1 (gather): x -> eh1 (hi/lo)
    {
        dim3 grid(H1 / 128, BB / 128, EE);
        gemm_mma<true, true><<<grid, 256, GEMM_SMEM>>>(
            xhi, xlo, ew1h, ew1l, eb1, nullptr, eh1h, eh1l,
            DD, H1, 0, offp, cntp, rowtokp, (long)H1 * DD, H1);
    }
    // Expert L2: eh1 -> eh2 (fp32)
    {
        dim3 grid(H2 / 128, BB / 128, EE);
        gemm_mma<false, false><<<grid, 256, GEMM_SMEM>>>(
            eh1h, eh1l, ew2h, ew2l, eb2, eh2, nullptr, nullptr,
            H1, H2, 0, offp, cntp, nullptr, (long)H2 * H1, H2);
    }
    // Expert L3 + gated combine
    {
        dim3 grid(1, BB / 4, EE);
        expert_l3_combine<<<grid, 256>>>(eh2, eW3, eb3, out_final);
    }
}